// round 1
// baseline (speedup 1.0000x reference)
#include <cuda_runtime.h>

// TreePositionalEncodings — sm_100a
//
// out[b, s, j]:
//   s == 0 or s > 1364            -> 0
//   j >= 1020                      -> 0
//   else                           -> positions[0, s-1, j/51] * w[j]
// where w[j] = tanh(p[j%51])^((j/51)/4) * sqrt((1-tanh^2)*1024/2)
//
// positions is identical across the batch dim (reference broadcasts one tree
// table), so each CTA computes its float4 once and stores it 32x.

#define D_MODEL   1024
#define MAX_LEN   2048
#define N_NODES   1364
#define BATCH     32
#define N_FEAT    51
#define N_DW      20
#define TREE_W    4

__device__ __align__(16) float g_w[D_MODEL];

__global__ void precompute_w_kernel(const float* __restrict__ p) {
    int j = threadIdx.x;            // 0..1023
    float w = 0.0f;
    if (j < N_DW * N_FEAT) {
        int f = j % N_FEAT;
        int level = (j / N_FEAT) / TREE_W;     // 0..4
        float tp = tanhf(p[f]);
        float norm = sqrtf((1.0f - tp * tp) * (0.5f * (float)D_MODEL));
        float pw = 1.0f;
        #pragma unroll 1
        for (int l = 0; l < level; l++) pw *= tp;
        w = pw * norm;
    }
    g_w[j] = w;
}

__global__ void __launch_bounds__(256) tree_pos_enc_kernel(
    const float* __restrict__ positions,   // [BS, N_NODES, N_DW]; b=0 slice used
    float* __restrict__ out)               // [BS, MAX_LEN, D_MODEL]
{
    __shared__ float s_pos[N_DW];

    const int s   = blockIdx.x;            // sequence index 0..2047
    const int tid = threadIdx.x;           // 0..255, each owns 4 features

    const bool active = (s >= 1) && (s <= N_NODES);

    if (active && tid < N_DW) {
        s_pos[tid] = positions[(size_t)(s - 1) * N_DW + tid];
    }
    __syncthreads();

    float4 v = make_float4(0.f, 0.f, 0.f, 0.f);
    if (active) {
        const int j = tid * 4;
        const float4 w4 = *reinterpret_cast<const float4*>(&g_w[j]);
        float wv[4] = {w4.x, w4.y, w4.z, w4.w};
        float r[4];
        #pragma unroll
        for (int e = 0; e < 4; e++) {
            int jj = j + e;
            int dw = jj / N_FEAT;                        // const divisor -> mul/shift
            float pv = (dw < N_DW) ? s_pos[dw] : 0.0f;   // tail pad features
            r[e] = pv * wv[e];
        }
        v = make_float4(r[0], r[1], r[2], r[3]);
    }

    // Store the same float4 for every batch: 32 independent STG.128.
    float4* o = reinterpret_cast<float4*>(out)
              + (size_t)s * (D_MODEL / 4) + tid;
    const size_t bstride = (size_t)MAX_LEN * (D_MODEL / 4);
    #pragma unroll 8
    for (int b = 0; b < BATCH; b++) {
        o[(size_t)b * bstride] = v;
    }
}

extern "C" void kernel_launch(void* const* d_in, const int* in_sizes, int n_in,
                              void* d_out, int out_size) {
    const float* p         = (const float*)d_in[0];   // [64]
    const float* positions = (const float*)d_in[1];   // [32, 1364, 20]
    float* out             = (float*)d_out;           // [32, 2048, 1024]

    precompute_w_kernel<<<1, D_MODEL>>>(p);
    tree_pos_enc_kernel<<<MAX_LEN, 256>>>(positions, out);
}

// round 2
// speedup vs baseline: 1.0421x; 1.0421x over previous
#include <cuda_runtime.h>

// TreePositionalEncodings — sm_100a, single fused kernel.
//
// out[b, s, j]:
//   s == 0 or s > 1364  -> 0
//   j >= 1020           -> 0
//   else                -> positions[0, s-1, j/51] * w[j]
// w[j] = tanh(p[j%51])^((j/51)/4) * sqrt((1-tanh^2)*1024/2)
//
// positions is identical across the batch dim, so each CTA (one per sequence
// position s) computes its float4 once and streams it out 32x (one per batch).
// Weight table is rebuilt per-CTA from 51 tanhf — hidden under the store
// stream (issue util ~6.5% when memory-bound).

#define D_MODEL   1024
#define MAX_LEN   2048
#define N_NODES   1364
#define BATCH     32
#define N_FEAT    51
#define N_DW      20
#define TREE_W    4

__global__ void __launch_bounds__(256) tree_pos_enc_fused_kernel(
    const float* __restrict__ p,           // [64], first 51 used
    const float* __restrict__ positions,   // [BS, N_NODES, N_DW]; b=0 slice used
    float* __restrict__ out)               // [BS, MAX_LEN, D_MODEL]
{
    __shared__ float s_pos[N_DW];
    __shared__ float s_tp[N_FEAT];
    __shared__ float s_norm[N_FEAT];

    const int s   = blockIdx.x;            // 0..2047
    const int tid = threadIdx.x;           // 0..255

    const bool active = (s >= 1) && (s <= N_NODES);

    if (active) {
        if (tid < N_FEAT) {
            float tp = tanhf(p[tid]);
            s_tp[tid]   = tp;
            s_norm[tid] = sqrtf((1.0f - tp * tp) * (0.5f * (float)D_MODEL));
        }
        if (tid >= 64 && tid < 64 + N_DW) {
            s_pos[tid - 64] = positions[(size_t)(s - 1) * N_DW + (tid - 64)];
        }
    }
    __syncthreads();

    float4 v = make_float4(0.f, 0.f, 0.f, 0.f);
    if (active) {
        const int j = tid * 4;
        float r[4];
        #pragma unroll
        for (int e = 0; e < 4; e++) {
            int jj = j + e;
            int f  = jj % N_FEAT;          // const-divisor -> magic mul
            int dw = jj / N_FEAT;          // 0..20 (dw==20 only for jj>=1020)
            float w = 0.0f;
            if (dw < N_DW) {
                int level = dw >> 2;       // 0..4
                float tp = s_tp[f];
                w = s_norm[f];
                #pragma unroll 1
                for (int l = 0; l < level; l++) w *= tp;
                w *= s_pos[dw];
            }
            r[e] = w;
        }
        v = make_float4(r[0], r[1], r[2], r[3]);
    }

    // Stream the same float4 to every batch: 32 independent STG.128,
    // evict-first L2 policy (output is never re-read).
    float4* o = reinterpret_cast<float4*>(out)
              + (size_t)s * (D_MODEL / 4) + tid;
    const size_t bstride = (size_t)MAX_LEN * (D_MODEL / 4);
    #pragma unroll 8
    for (int b = 0; b < BATCH; b++) {
        __stcs(o + (size_t)b * bstride, v);
    }
}

extern "C" void kernel_launch(void* const* d_in, const int* in_sizes, int n_in,
                              void* d_out, int out_size) {
    const float* p         = (const float*)d_in[0];   // [64]
    const float* positions = (const float*)d_in[1];   // [32, 1364, 20]
    float* out             = (float*)d_out;           // [32, 2048, 1024]

    tree_pos_enc_fused_kernel<<<MAX_LEN, 256>>>(p, positions, out);
}

// round 3
// speedup vs baseline: 1.0856x; 1.0417x over previous
#include <cuda_runtime.h>

// TreePositionalEncodings — sm_100a, single fused kernel, R3.
//
// out[b, s, j]:
//   s == 0 or s > 1364  -> 0
//   j >= 1020           -> 0
//   else                -> positions[0, s-1, j/51] * w[j]
// w[j] = tanh(p[j%51])^((j/51)/4) * sqrt((1-tanh^2)*1024/2)
//
// R3 change: block = one CONTIGUOUS 128KB strip (one batch b, 32 consecutive
// sequence rows). Each block streams memset-style through its strip instead of
// scattering 32 stores at 8MB stride — targets DRAM open-row locality
// (R2: DRAM=60.4% vs ~80%+ for linear writes).

#define D_MODEL   1024
#define MAX_LEN   2048
#define N_NODES   1364
#define BATCH     32
#define N_FEAT    51
#define N_DW      20
#define STRIP     32          // rows per block
#define STRIPS_PER_B (MAX_LEN / STRIP)   // 64

__global__ void __launch_bounds__(256) tree_pos_enc_strip_kernel(
    const float* __restrict__ p,           // [64], first 51 used
    const float* __restrict__ positions,   // [BS, N_NODES, N_DW]; b=0 slice used
    float* __restrict__ out)               // [BS, MAX_LEN, D_MODEL]
{
    __shared__ float s_tp[N_FEAT];
    __shared__ float s_norm[N_FEAT];
    __shared__ float s_pos[STRIP][N_DW];

    const int bx  = blockIdx.x;            // 0..2047
    const int b   = bx >> 6;               // batch 0..31
    const int s0  = (bx & (STRIPS_PER_B - 1)) * STRIP;  // first row of strip
    const int tid = threadIdx.x;           // 0..255, each owns 4 features

    // Weight params (51 tanhf, hidden under the store stream).
    if (tid < N_FEAT) {
        float tp = tanhf(p[tid]);
        s_tp[tid]   = tp;
        s_norm[tid] = sqrtf((1.0f - tp * tp) * (0.5f * (float)D_MODEL));
    }
    // Position rows for this strip; inactive rows (s==0 or s>N_NODES) -> 0,
    // so the store loop below is uniform and emits zeros for them.
    #pragma unroll
    for (int k = 0; k < (STRIP * N_DW + 255) / 256; k++) {
        int idx = tid + k * 256;
        if (idx < STRIP * N_DW) {
            int r = idx / N_DW, c = idx % N_DW;
            int s = s0 + r;
            float v = 0.0f;
            if (s >= 1 && s <= N_NODES)
                v = positions[(size_t)(s - 1) * N_DW + c];
            s_pos[r][c] = v;
        }
    }
    __syncthreads();

    // Per-thread loop-invariant weights + dw indices (4 features each).
    const int j = tid * 4;
    float w[4];
    int   dwv[4];
    #pragma unroll
    for (int e = 0; e < 4; e++) {
        int jj = j + e;
        int f  = jj % N_FEAT;              // const divisor -> magic mul
        int dw = jj / N_FEAT;              // 20 only for jj >= 1020 (zero pad)
        dwv[e] = (dw < N_DW) ? dw : 0;
        float ww = 0.0f;
        if (dw < N_DW) {
            int level = dw >> 2;           // 0..4
            float tp = s_tp[f];
            ww = s_norm[f];
            #pragma unroll 1
            for (int l = 0; l < level; l++) ww *= tp;
        }
        w[e] = ww;
    }

    // Stream 32 consecutive 4KB rows: fully sequential 128KB per block.
    float4* o = reinterpret_cast<float4*>(out)
              + (size_t)b * (MAX_LEN * (D_MODEL / 4))
              + (size_t)s0 * (D_MODEL / 4) + tid;
    #pragma unroll 8
    for (int r = 0; r < STRIP; r++) {
        float4 v;
        v.x = w[0] * s_pos[r][dwv[0]];
        v.y = w[1] * s_pos[r][dwv[1]];
        v.z = w[2] * s_pos[r][dwv[2]];
        v.w = w[3] * s_pos[r][dwv[3]];
        __stcs(o + (size_t)r * (D_MODEL / 4), v);
    }
}

extern "C" void kernel_launch(void* const* d_in, const int* in_sizes, int n_in,
                              void* d_out, int out_size) {
    const float* p         = (const float*)d_in[0];   // [64]
    const float* positions = (const float*)d_in[1];   // [32, 1364, 20]
    float* out             = (float*)d_out;           // [32, 2048, 1024]

    tree_pos_enc_strip_kernel<<<BATCH * STRIPS_PER_B, 256>>>(p, positions, out);
}